// round 1
// baseline (speedup 1.0000x reference)
#include <cuda_runtime.h>
#include <cuda_bf16.h>

// Problem dims (fixed for this problem instance)
//   x:          (B=2, V=8, T=4, N=1024, D=16, F_IN=64)  float32
//   var_idx:    (B, V)                                   int32
//   core:       (RV=4, R=16, R=16)                       float32
//   factor_vars:(NVAR=8, RV=4)                           float32
//   fac_in:     (R=16, F_IN=64)                          float32
//   fac_out:    (R=16, F_OUT=64)                         float32
//   out:        (B, V, T, N, D, F_OUT=64)                float32
//
// Math per row r=(b,v,t,n,d):
//   W[B][C]  = sum_A factor_vars[var_idx[b,v]][A] * core[A][B][C]
//   Wo[B][e] = sum_C W[B][C] * fac_out[C][e]
//   y1[B]    = sum_a x[r][a] * fac_in[B][a]
//   out[r][e]= sum_B y1[B] * Wo[B][e]

typedef unsigned long long u64;

__device__ __forceinline__ u64 pack2(float lo, float hi) {
    u64 r;
    asm("mov.b64 %0, {%1, %2};" : "=l"(r) : "f"(lo), "f"(hi));
    return r;
}
__device__ __forceinline__ void unpack2(u64 v, float& lo, float& hi) {
    asm("mov.b64 {%0, %1}, %2;" : "=f"(lo), "=f"(hi) : "l"(v));
}
// Packed fp32x2 FMA (Blackwell): d = a*b + c elementwise on two fp32 lanes.
__device__ __forceinline__ u64 ffma2(u64 a, u64 b, u64 c) {
    u64 d;
    asm("fma.rn.f32x2 %0, %1, %2, %3;" : "=l"(d) : "l"(a), "l"(b), "l"(c));
    return d;
}

static constexpr int RV_     = 4;
static constexpr int R_      = 16;
static constexpr int FIN_    = 64;
static constexpr int FOUT_   = 64;
static constexpr int ROWS_PER_BV = 4 * 1024 * 16;  // T*N*D = 65536
static constexpr int THREADS = 256;
static constexpr long long TOTAL_ROWS = 2LL * 8 * 4 * 1024 * 16;  // 1048576

__global__ void __launch_bounds__(THREADS)
tucker_fac_kernel(const float* __restrict__ x,
                  const int*   __restrict__ var_idx,
                  const float* __restrict__ core,
                  const float* __restrict__ factor_vars,
                  const float* __restrict__ fac_in,
                  const float* __restrict__ fac_out,
                  float* __restrict__ out)
{
    __shared__ __align__(16) float s_fin[FIN_][R_];   // [a][B] = fac_in[B][a] (transposed)
    __shared__ __align__(16) float s_Wo[R_][FOUT_];   // [B][e]
    __shared__ float s_W[R_][R_];                     // [B][C]

    const int tid = threadIdx.x;
    const long long row0 = (long long)blockIdx.x * THREADS;
    const int bv = (int)(row0 >> 16);   // ROWS_PER_BV = 65536 rows per (b,v); 256 | 65536

    // ---------- Per-block weight setup ----------
    {
        const int vi = var_idx[bv];
        const float fv0 = factor_vars[vi * RV_ + 0];
        const float fv1 = factor_vars[vi * RV_ + 1];
        const float fv2 = factor_vars[vi * RV_ + 2];
        const float fv3 = factor_vars[vi * RV_ + 3];
        const int Bc = tid >> 4, Cc = tid & 15;     // 256 threads -> 16x16 entries
        float w = fv0 * core[(0 * R_ + Bc) * R_ + Cc]
                + fv1 * core[(1 * R_ + Bc) * R_ + Cc]
                + fv2 * core[(2 * R_ + Bc) * R_ + Cc]
                + fv3 * core[(3 * R_ + Bc) * R_ + Cc];
        s_W[Bc][Cc] = w;

        // fac_in transpose into SMEM: s_fin[a][B] = fac_in[B*64 + a]
        #pragma unroll
        for (int k = 0; k < 4; ++k) {
            int i = tid + k * 256;       // 0..1023
            int a = i >> 4;
            int Bq = i & 15;
            s_fin[a][Bq] = fac_in[Bq * FIN_ + a];
        }
    }
    __syncthreads();

    // Wo = W @ fac_out  (16x64), 4 entries per thread
    {
        #pragma unroll
        for (int k = 0; k < 4; ++k) {
            int i = tid + k * 256;       // 0..1023
            int Bc = i >> 6;
            int e  = i & 63;
            float acc = 0.0f;
            #pragma unroll
            for (int C = 0; C < R_; ++C)
                acc += s_W[Bc][C] * fac_out[C * FOUT_ + e];
            s_Wo[Bc][e] = acc;
        }
    }
    __syncthreads();

    // ---------- Per-row compute ----------
    const long long row = row0 + tid;
    const float4* xp = reinterpret_cast<const float4*>(x + row * 64);

    // Front-batched load of the 64-feature input row (MLP = 16)
    float4 xr[16];
    #pragma unroll
    for (int q = 0; q < 16; ++q) xr[q] = xp[q];

    // Phase 1: y1[B] = sum_a x[a] * fac_in[B][a]   (packed pairs over B)
    u64 acc1[8];
    #pragma unroll
    for (int j = 0; j < 8; ++j) acc1[j] = 0ULL;

    #pragma unroll
    for (int q = 0; q < 16; ++q) {
        const float vals[4] = { xr[q].x, xr[q].y, xr[q].z, xr[q].w };
        #pragma unroll
        for (int c = 0; c < 4; ++c) {
            const int a = q * 4 + c;
            const u64 xa = pack2(vals[c], vals[c]);
            const ulonglong2* wr = reinterpret_cast<const ulonglong2*>(&s_fin[a][0]);
            #pragma unroll
            for (int h = 0; h < 4; ++h) {
                const ulonglong2 w2 = wr[h];             // LDS.128 broadcast
                acc1[2 * h]     = ffma2(xa, w2.x, acc1[2 * h]);
                acc1[2 * h + 1] = ffma2(xa, w2.y, acc1[2 * h + 1]);
            }
        }
    }

    // Unpack y1 and re-broadcast as pairs
    float y1[16];
    #pragma unroll
    for (int j = 0; j < 8; ++j) unpack2(acc1[j], y1[2 * j], y1[2 * j + 1]);

    u64 yp[16];
    #pragma unroll
    for (int Bq = 0; Bq < 16; ++Bq) yp[Bq] = pack2(y1[Bq], y1[Bq]);

    // Phase 2: out[e] = sum_B y1[B] * Wo[B][e], 16 outputs (8 pairs) at a time
    float4* op = reinterpret_cast<float4*>(out + row * 64);
    #pragma unroll
    for (int ec = 0; ec < 4; ++ec) {
        u64 acc[8];
        #pragma unroll
        for (int j = 0; j < 8; ++j) acc[j] = 0ULL;

        #pragma unroll
        for (int Bq = 0; Bq < 16; ++Bq) {
            const ulonglong2* wr =
                reinterpret_cast<const ulonglong2*>(&s_Wo[Bq][ec * 16]);
            #pragma unroll
            for (int h = 0; h < 4; ++h) {
                const ulonglong2 w2 = wr[h];             // LDS.128 broadcast
                acc[2 * h]     = ffma2(yp[Bq], w2.x, acc[2 * h]);
                acc[2 * h + 1] = ffma2(yp[Bq], w2.y, acc[2 * h + 1]);
            }
        }

        #pragma unroll
        for (int h = 0; h < 4; ++h) {
            union { u64 u[2]; float4 f; } cv;
            cv.u[0] = acc[2 * h];
            cv.u[1] = acc[2 * h + 1];
            op[ec * 4 + h] = cv.f;                       // STG.128
        }
    }
}

extern "C" void kernel_launch(void* const* d_in, const int* in_sizes, int n_in,
                              void* d_out, int out_size)
{
    const float* x           = (const float*)d_in[0];
    const int*   var_idx     = (const int*)  d_in[1];
    const float* core        = (const float*)d_in[2];
    const float* factor_vars = (const float*)d_in[3];
    const float* fac_in      = (const float*)d_in[4];
    const float* fac_out     = (const float*)d_in[5];
    float* out = (float*)d_out;

    const int grid = (int)(TOTAL_ROWS / THREADS);  // 4096
    tucker_fac_kernel<<<grid, THREADS>>>(x, var_idx, core, factor_vars,
                                         fac_in, fac_out, out);
}

// round 3
// speedup vs baseline: 1.2386x; 1.2386x over previous
#include <cuda_runtime.h>
#include <cuda_bf16.h>

// TuckerFacLayer — register-blocked FFMA2 version (4 rows/thread).
//   x:          (B=2, V=8, T=4, N=1024, D=16, F_IN=64)  float32
//   var_idx:    (B, V)                                   int32
//   core:       (RV=4, R=16, R=16)                       float32
//   factor_vars:(NVAR=8, RV=4)                           float32
//   fac_in:     (R=16, F_IN=64)                          float32
//   fac_out:    (R=16, F_OUT=64)                         float32
//   out:        (B, V, T, N, D, F_OUT=64)                float32
//
// Per row r: y1[B] = sum_a x[a]*fac_in[B][a];  out[e] = sum_B y1[B]*Wo[B][e]
// where Wo[B][e] = sum_C (sum_A fv[A]*core[A][B][C]) * fac_out[C][e].

typedef unsigned long long u64;

__device__ __forceinline__ u64 pack2(float lo, float hi) {
    u64 r;
    asm("mov.b64 %0, {%1, %2};" : "=l"(r) : "f"(lo), "f"(hi));
    return r;
}
__device__ __forceinline__ void unpack2(u64 v, float& lo, float& hi) {
    asm("mov.b64 {%0, %1}, %2;" : "=f"(lo), "=f"(hi) : "l"(v));
}
// Packed fp32x2 FMA: d = a*b + c on two fp32 lanes.
__device__ __forceinline__ u64 ffma2(u64 a, u64 b, u64 c) {
    u64 d;
    asm("fma.rn.f32x2 %0, %1, %2, %3;" : "=l"(d) : "l"(a), "l"(b), "l"(c));
    return d;
}

static constexpr int RV_   = 4;
static constexpr int R_    = 16;
static constexpr int FIN_  = 64;
static constexpr int FOUT_ = 64;
static constexpr int THREADS = 128;
static constexpr int ROWS    = 4;                       // rows per thread
static constexpr int ROWS_PER_BLOCK = THREADS * ROWS;   // 512
static constexpr long long TOTAL_ROWS = 2LL * 8 * 4 * 1024 * 16;  // 1048576

__global__ void __launch_bounds__(THREADS)
tucker_fac_kernel(const float* __restrict__ x,
                  const int*   __restrict__ var_idx,
                  const float* __restrict__ core,
                  const float* __restrict__ factor_vars,
                  const float* __restrict__ fac_in,
                  const float* __restrict__ fac_out,
                  float* __restrict__ out)
{
    __shared__ __align__(16) float s_fin[FIN_][R_];   // [a][B] = fac_in[B][a]
    __shared__ __align__(16) float s_Wo[R_][FOUT_];   // [B][e]
    __shared__ float s_W[R_][R_];                     // [B][C]

    const int tid = threadIdx.x;
    const long long row_base = (long long)blockIdx.x * ROWS_PER_BLOCK;
    const int bv = (int)(row_base >> 16);   // 65536 rows per (b,v); 512 | 65536

    // ---------- Per-block weight setup ----------
    {
        const int vi = var_idx[bv];
        const float fv0 = factor_vars[vi * RV_ + 0];
        const float fv1 = factor_vars[vi * RV_ + 1];
        const float fv2 = factor_vars[vi * RV_ + 2];
        const float fv3 = factor_vars[vi * RV_ + 3];
        #pragma unroll
        for (int k = 0; k < 2; ++k) {               // 256 W entries / 128 thr
            const int i = tid + k * THREADS;
            const int Bc = i >> 4, Cc = i & 15;
            s_W[Bc][Cc] = fv0 * core[(0 * R_ + Bc) * R_ + Cc]
                        + fv1 * core[(1 * R_ + Bc) * R_ + Cc]
                        + fv2 * core[(2 * R_ + Bc) * R_ + Cc]
                        + fv3 * core[(3 * R_ + Bc) * R_ + Cc];
        }
        #pragma unroll
        for (int k = 0; k < 8; ++k) {               // 1024 fin entries
            const int i = tid + k * THREADS;
            const int a = i >> 4, Bq = i & 15;
            s_fin[a][Bq] = fac_in[Bq * FIN_ + a];
        }
    }
    __syncthreads();

    // Wo = W @ fac_out  (16x64)
    {
        #pragma unroll
        for (int k = 0; k < 8; ++k) {
            const int i = tid + k * THREADS;
            const int Bc = i >> 6, e = i & 63;
            float acc = 0.0f;
            #pragma unroll
            for (int C = 0; C < R_; ++C)
                acc += s_W[Bc][C] * fac_out[C * FOUT_ + e];
            s_Wo[Bc][e] = acc;
        }
    }
    __syncthreads();

    // ---------- Per-row compute: 4 rows per thread, strided by THREADS ----------
    const long long r0 = row_base + tid;            // rows r0 + j*THREADS, j=0..3

    const float4* xp0 = reinterpret_cast<const float4*>(x + (r0 + 0 * THREADS) * 64);
    const float4* xp1 = reinterpret_cast<const float4*>(x + (r0 + 1 * THREADS) * 64);
    const float4* xp2 = reinterpret_cast<const float4*>(x + (r0 + 2 * THREADS) * 64);
    const float4* xp3 = reinterpret_cast<const float4*>(x + (r0 + 3 * THREADS) * 64);

    // Phase 1: y1[r][B] = sum_a x[r][a] * s_fin[a][B]
    u64 acc1[ROWS][8];
    #pragma unroll
    for (int r = 0; r < ROWS; ++r)
        #pragma unroll
        for (int j = 0; j < 8; ++j) acc1[r][j] = 0ULL;

    #pragma unroll
    for (int q = 0; q < 16; ++q) {
        float4 xq[ROWS];
        xq[0] = xp0[q]; xq[1] = xp1[q]; xq[2] = xp2[q]; xq[3] = xp3[q];

        #pragma unroll
        for (int c = 0; c < 4; ++c) {
            const int a = q * 4 + c;
            const ulonglong2* wr = reinterpret_cast<const ulonglong2*>(&s_fin[a][0]);
            const ulonglong2 w01 = wr[0], w23 = wr[1], w45 = wr[2], w67 = wr[3];
            #pragma unroll
            for (int r = 0; r < ROWS; ++r) {
                const float v = (c == 0) ? xq[r].x : (c == 1) ? xq[r].y
                              : (c == 2) ? xq[r].z : xq[r].w;
                const u64 xa = pack2(v, v);
                acc1[r][0] = ffma2(xa, w01.x, acc1[r][0]);
                acc1[r][1] = ffma2(xa, w01.y, acc1[r][1]);
                acc1[r][2] = ffma2(xa, w23.x, acc1[r][2]);
                acc1[r][3] = ffma2(xa, w23.y, acc1[r][3]);
                acc1[r][4] = ffma2(xa, w45.x, acc1[r][4]);
                acc1[r][5] = ffma2(xa, w45.y, acc1[r][5]);
                acc1[r][6] = ffma2(xa, w67.x, acc1[r][6]);
                acc1[r][7] = ffma2(xa, w67.y, acc1[r][7]);
            }
        }
    }

    // Unpack y1 into floats (acc1 registers die here)
    float y[ROWS][16];
    #pragma unroll
    for (int r = 0; r < ROWS; ++r)
        #pragma unroll
        for (int j = 0; j < 8; ++j)
            unpack2(acc1[r][j], y[r][2 * j], y[r][2 * j + 1]);

    // Phase 2: out[r][e] = sum_B y[r][B] * s_Wo[B][e], 16 outputs per chunk
    float4* op0 = reinterpret_cast<float4*>(out + (r0 + 0 * THREADS) * 64);
    float4* op1 = reinterpret_cast<float4*>(out + (r0 + 1 * THREADS) * 64);
    float4* op2 = reinterpret_cast<float4*>(out + (r0 + 2 * THREADS) * 64);
    float4* op3 = reinterpret_cast<float4*>(out + (r0 + 3 * THREADS) * 64);

    #pragma unroll
    for (int ec = 0; ec < 4; ++ec) {
        u64 acc2[ROWS][8];
        #pragma unroll
        for (int r = 0; r < ROWS; ++r)
            #pragma unroll
            for (int j = 0; j < 8; ++j) acc2[r][j] = 0ULL;

        #pragma unroll
        for (int Bq = 0; Bq < 16; ++Bq) {
            const ulonglong2* wr =
                reinterpret_cast<const ulonglong2*>(&s_Wo[Bq][ec * 16]);
            const ulonglong2 w01 = wr[0], w23 = wr[1], w45 = wr[2], w67 = wr[3];
            #pragma unroll
            for (int r = 0; r < ROWS; ++r) {
                const u64 yb = pack2(y[r][Bq], y[r][Bq]);
                acc2[r][0] = ffma2(yb, w01.x, acc2[r][0]);
                acc2[r][1] = ffma2(yb, w01.y, acc2[r][1]);
                acc2[r][2] = ffma2(yb, w23.x, acc2[r][2]);
                acc2[r][3] = ffma2(yb, w23.y, acc2[r][3]);
                acc2[r][4] = ffma2(yb, w45.x, acc2[r][4]);
                acc2[r][5] = ffma2(yb, w45.y, acc2[r][5]);
                acc2[r][6] = ffma2(yb, w67.x, acc2[r][6]);
                acc2[r][7] = ffma2(yb, w67.y, acc2[r][7]);
            }
        }

        #pragma unroll
        for (int r = 0; r < ROWS; ++r) {
            float4* op = (r == 0) ? op0 : (r == 1) ? op1 : (r == 2) ? op2 : op3;
            #pragma unroll
            for (int h = 0; h < 4; ++h) {
                union { u64 u[2]; float4 f; } cv;
                cv.u[0] = acc2[r][2 * h];
                cv.u[1] = acc2[r][2 * h + 1];
                op[ec * 4 + h] = cv.f;              // STG.128
            }
        }
    }
}

extern "C" void kernel_launch(void* const* d_in, const int* in_sizes, int n_in,
                              void* d_out, int out_size)
{
    const float* x           = (const float*)d_in[0];
    const int*   var_idx     = (const int*)  d_in[1];
    const float* core        = (const float*)d_in[2];
    const float* factor_vars = (const float*)d_in[3];
    const float* fac_in      = (const float*)d_in[4];
    const float* fac_out     = (const float*)d_in[5];
    float* out = (float*)d_out;

    const int grid = (int)(TOTAL_ROWS / ROWS_PER_BLOCK);  // 2048
    tucker_fac_kernel<<<grid, THREADS>>>(x, var_idx, core, factor_vars,
                                         fac_in, fac_out, out);
}